// round 1
// baseline (speedup 1.0000x reference)
#include <cuda_runtime.h>
#include <cuda_bf16.h>

// Problem constants (from reference)
#define NN_MAX   100000
#define F        128          // IN_FEATS == HID == 128
#define NODE_T   32           // nodes per block in kernel A
#define EDGE_T   32           // edges per block in kernel B

// Scratch: A[n][j] = dot(W1[j][0:128],   h[n]) + b1[j]
//          B[n][j] = dot(W1[j][128:256], h[n])
__device__ float g_A[NN_MAX * F];
__device__ float g_B[NN_MAX * F];

// ---------------------------------------------------------------------------
// Kernel A: per-node transform. block = 128 threads (thread = output feat j),
// tile of 32 nodes per block. h tile staged in smem; W1 rows streamed via LDG
// (128 KB, L1/L2 resident across the tile loop).
// ---------------------------------------------------------------------------
__global__ void __launch_bounds__(F, 4)
node_transform_kernel(const float* __restrict__ h,
                      const float* __restrict__ W1,
                      const float* __restrict__ b1,
                      int n_nodes)
{
    __shared__ float hs[NODE_T][F];
    const int tid  = threadIdx.x;           // output feature j
    const int tile = blockIdx.x * NODE_T;

    #pragma unroll
    for (int i = 0; i < NODE_T; i++) {
        int n = tile + i;
        hs[i][tid] = (n < n_nodes) ? h[(size_t)n * F + tid] : 0.0f;
    }
    __syncthreads();

    float a[NODE_T], b[NODE_T];
    #pragma unroll
    for (int i = 0; i < NODE_T; i++) { a[i] = 0.0f; b[i] = 0.0f; }

    const float4* wu = (const float4*)(W1 + (size_t)tid * (2 * F));
    const float4* wv = (const float4*)(W1 + (size_t)tid * (2 * F) + F);

    for (int k4 = 0; k4 < F / 4; k4++) {
        float4 u = __ldg(wu + k4);
        float4 v = __ldg(wv + k4);
        #pragma unroll
        for (int i = 0; i < NODE_T; i++) {
            float4 hv = *(const float4*)&hs[i][k4 * 4];
            a[i] = fmaf(u.x, hv.x, fmaf(u.y, hv.y, fmaf(u.z, hv.z, fmaf(u.w, hv.w, a[i]))));
            b[i] = fmaf(v.x, hv.x, fmaf(v.y, hv.y, fmaf(v.z, hv.z, fmaf(v.w, hv.w, b[i]))));
        }
    }

    const float bias = b1[tid];
    #pragma unroll
    for (int i = 0; i < NODE_T; i++) {
        int n = tile + i;
        if (n < n_nodes) {
            g_A[(size_t)n * F + tid] = a[i] + bias;
            g_B[(size_t)n * F + tid] = b[i];
        }
    }
}

// ---------------------------------------------------------------------------
// Kernel B: per-edge fused MLP. block = 128 threads (thread = hid feat j),
// tile of 32 edges per block.
//   x[i][:] = relu(A[src] + B[dst])        (gather, coalesced per row)
//   y[i][j] = relu(dot(W2[j], x[i]) + b2[j])
//   out[i]  = sum_j y[i][j] * W3[j] + b3
// ---------------------------------------------------------------------------
__global__ void __launch_bounds__(F, 4)
edge_mlp_kernel(const int*   __restrict__ src,
                const int*   __restrict__ dst,
                const float* __restrict__ W2,
                const float* __restrict__ b2,
                const float* __restrict__ W3,
                const float* __restrict__ b3,
                float*       __restrict__ out,
                int n_edges)
{
    __shared__ float xs[EDGE_T][F];
    __shared__ float red[4][EDGE_T];

    const int tid  = threadIdx.x;            // hidden feature j
    const int lane = tid & 31;
    const int warp = tid >> 5;
    const int base = blockIdx.x * EDGE_T;

    // Gather + layer-1 combine + ReLU
    #pragma unroll
    for (int i = 0; i < EDGE_T; i++) {
        int e = base + i;
        if (e < n_edges) {
            int s = __ldg(&src[e]);
            int d = __ldg(&dst[e]);
            float v = g_A[(size_t)s * F + tid] + g_B[(size_t)d * F + tid];
            xs[i][tid] = fmaxf(v, 0.0f);
        } else {
            xs[i][tid] = 0.0f;
        }
    }
    __syncthreads();

    // Layer 2: y[i][tid] = dot(W2[tid], x[i])
    float acc[EDGE_T];
    #pragma unroll
    for (int i = 0; i < EDGE_T; i++) acc[i] = 0.0f;

    const float4* w2 = (const float4*)(W2 + (size_t)tid * F);
    for (int k4 = 0; k4 < F / 4; k4++) {
        float4 w = __ldg(w2 + k4);
        #pragma unroll
        for (int i = 0; i < EDGE_T; i++) {
            float4 xv = *(const float4*)&xs[i][k4 * 4];
            acc[i] = fmaf(w.x, xv.x, fmaf(w.y, xv.y, fmaf(w.z, xv.z, fmaf(w.w, xv.w, acc[i]))));
        }
    }

    // ReLU + layer-3 weight, then reduce over j (128 threads) per edge
    const float bias2 = b2[tid];
    const float w3v   = W3[tid];
    float part[EDGE_T];
    #pragma unroll
    for (int i = 0; i < EDGE_T; i++) {
        part[i] = fmaxf(acc[i] + bias2, 0.0f) * w3v;
    }

    // intra-warp butterfly reduce (all 32 edges)
    #pragma unroll
    for (int off = 16; off > 0; off >>= 1) {
        #pragma unroll
        for (int i = 0; i < EDGE_T; i++) {
            part[i] += __shfl_xor_sync(0xFFFFFFFFu, part[i], off);
        }
    }
    if (lane == 0) {
        #pragma unroll
        for (int i = 0; i < EDGE_T; i++) red[warp][i] = part[i];
    }
    __syncthreads();

    if (tid < EDGE_T) {
        int e = base + tid;
        if (e < n_edges) {
            float s = red[0][tid] + red[1][tid] + red[2][tid] + red[3][tid];
            out[e] = s + b3[0];
        }
    }
}

// ---------------------------------------------------------------------------
// kernel_launch: inputs (metadata order): h, src, dst, W1, b1, W2, b2, W3, b3
// output: score [n_edges, 1] float
// ---------------------------------------------------------------------------
extern "C" void kernel_launch(void* const* d_in, const int* in_sizes, int n_in,
                              void* d_out, int out_size)
{
    const float* h   = (const float*)d_in[0];
    const int*   src = (const int*)  d_in[1];
    const int*   dst = (const int*)  d_in[2];
    const float* W1  = (const float*)d_in[3];
    const float* b1  = (const float*)d_in[4];
    const float* W2  = (const float*)d_in[5];
    const float* b2  = (const float*)d_in[6];
    const float* W3  = (const float*)d_in[7];
    const float* b3  = (const float*)d_in[8];
    float*       out = (float*)d_out;

    const int n_nodes = in_sizes[0] / F;
    const int n_edges = in_sizes[1];

    const int gridA = (n_nodes + NODE_T - 1) / NODE_T;
    node_transform_kernel<<<gridA, F>>>(h, W1, b1, n_nodes);

    const int gridB = (n_edges + EDGE_T - 1) / EDGE_T;
    edge_mlp_kernel<<<gridB, F>>>(src, dst, W2, b2, W3, b3, out, n_edges);
}

// round 3
// speedup vs baseline: 2.1627x; 2.1627x over previous
#include <cuda_runtime.h>
#include <cuda_bf16.h>
#include <cstdint>

#define NN_MAX   100000
#define F        128
#define PAD      136      // fp32 words per row in smem tiles (bank-conflict tuned)
#define W1PAD    264      // pitch for node-kernel W1 tile (256 outputs + pad)

// Scratch: A[n][j] = W1[:, :128] @ h[n] + b1 ; B[n][j] = W1[:, 128:] @ h[n]
__device__ float g_A[NN_MAX * F];
__device__ float g_B[NN_MAX * F];

// ---------------------------------------------------------------------------
// helpers
// ---------------------------------------------------------------------------
__device__ __forceinline__ uint32_t f2tf32(float f) {
    uint32_t r;
    asm("cvt.rna.tf32.f32 %0, %1;" : "=r"(r) : "f"(f));
    return r;
}

// D += A*B, m16n8k8 tf32 (row.col). acc c0..c3 fp32.
__device__ __forceinline__ void mma_tf32(float& c0, float& c1, float& c2, float& c3,
                                         uint32_t a0, uint32_t a1, uint32_t a2, uint32_t a3,
                                         uint32_t b0, uint32_t b1)
{
    asm volatile(
        "mma.sync.aligned.m16n8k8.row.col.f32.tf32.tf32.f32 "
        "{%0,%1,%2,%3}, {%4,%5,%6,%7}, {%8,%9}, {%0,%1,%2,%3};\n"
        : "+f"(c0), "+f"(c1), "+f"(c2), "+f"(c3)
        : "r"(a0), "r"(a1), "r"(a2), "r"(a3), "r"(b0), "r"(b1));
}

// ===========================================================================
// Node kernel: [A|B] = h @ W1^T  (128 nodes x 256 outs x K=128 per block)
// smem: Hs[128][PAD] (tf32), W1s[128][W1PAD] (tf32, W1 transposed), b1s[128]
// ===========================================================================
#define NODE_SMEM_U32  (128 * PAD + 128 * W1PAD + 128)
#define NODE_SMEM_B    (NODE_SMEM_U32 * 4)

__global__ void __launch_bounds__(256, 1)
node_mma_kernel(const float* __restrict__ h,
                const float* __restrict__ W1,
                const float* __restrict__ b1,
                int n_nodes)
{
    extern __shared__ uint32_t sm[];
    uint32_t* Hs  = sm;                       // 128*PAD
    uint32_t* W1s = sm + 128 * PAD;           // 128*W1PAD
    float*    b1s = (float*)(sm + 128 * PAD + 128 * W1PAD);

    const int tid  = threadIdx.x;
    const int lane = tid & 31;
    const int warp = tid >> 5;
    const int g    = lane >> 2;
    const int t    = lane & 3;
    const int base = blockIdx.x * 128;

    if (tid < 128) b1s[tid] = b1[tid];

    // stage W1 transposed: W1s[k][j2] = W1[j2&127][(j2>>7)*128 + k]
    {
        const int j2 = tid;                            // 0..255
        const float* wrow = W1 + (size_t)(j2 & 127) * 256 + ((j2 >> 7) << 7);
        #pragma unroll
        for (int k4 = 0; k4 < 32; k4++) {
            float4 w = __ldg((const float4*)wrow + k4);
            int k = k4 * 4;
            W1s[(k + 0) * W1PAD + j2] = f2tf32(w.x);
            W1s[(k + 1) * W1PAD + j2] = f2tf32(w.y);
            W1s[(k + 2) * W1PAD + j2] = f2tf32(w.z);
            W1s[(k + 3) * W1PAD + j2] = f2tf32(w.w);
        }
    }

    // stage h tile: row r, half hh covers cols [hh*64, hh*64+64)
    {
        const int r  = tid >> 1;
        const int hh = tid & 1;
        const int n  = base + r;
        const bool ok = (n < n_nodes);
        const float4* hr = (const float4*)(h + (size_t)n * F) + hh * 16;
        #pragma unroll
        for (int q = 0; q < 16; q++) {
            uint32_t x0 = 0, x1 = 0, x2 = 0, x3 = 0;
            if (ok) {
                float4 v = __ldg(hr + q);
                x0 = f2tf32(v.x); x1 = f2tf32(v.y);
                x2 = f2tf32(v.z); x3 = f2tf32(v.w);
            }
            uint32_t* p = &Hs[r * PAD + hh * 64 + q * 4];
            p[0] = x0; p[1] = x1; p[2] = x2; p[3] = x3;
        }
    }
    __syncthreads();

    const int mq = warp & 3;
    const int m0 = mq * 32;

    // each warp does 2 n-tiles of 64 cols: np = (warp>>2), (warp>>2)+2
    for (int np = (warp >> 2); np < 4; np += 2) {
        const int nb = np * 64;
        float acc[2][8][4];
        #pragma unroll
        for (int im = 0; im < 2; im++)
            #pragma unroll
            for (int in = 0; in < 8; in++)
                #pragma unroll
                for (int c = 0; c < 4; c++) acc[im][in][c] = 0.0f;

        #pragma unroll
        for (int k8 = 0; k8 < 16; k8++) {
            const int kc = k8 * 8;
            uint32_t af[2][4];
            #pragma unroll
            for (int im = 0; im < 2; im++) {
                const int r = m0 + im * 16 + g;
                af[im][0] = Hs[(r)     * PAD + kc + t];
                af[im][1] = Hs[(r + 8) * PAD + kc + t];
                af[im][2] = Hs[(r)     * PAD + kc + t + 4];
                af[im][3] = Hs[(r + 8) * PAD + kc + t + 4];
            }
            #pragma unroll
            for (int in = 0; in < 8; in++) {
                const int nc = nb + in * 8 + g;
                uint32_t b0 = W1s[(kc + t)     * W1PAD + nc];
                uint32_t b1r = W1s[(kc + t + 4) * W1PAD + nc];
                #pragma unroll
                for (int im = 0; im < 2; im++)
                    mma_tf32(acc[im][in][0], acc[im][in][1], acc[im][in][2], acc[im][in][3],
                             af[im][0], af[im][1], af[im][2], af[im][3], b0, b1r);
            }
        }

        // epilogue: write A/B (bias only for A side)
        #pragma unroll
        for (int im = 0; im < 2; im++) {
            const int r0 = m0 + im * 16 + g;
            const int n0 = base + r0;
            const int n1 = n0 + 8;
            #pragma unroll
            for (int in = 0; in < 8; in++) {
                const int col0 = nb + in * 8 + 2 * t;     // col1 = col0+1, same side
                const bool isA = (col0 < 128);
                const float bb0 = isA ? b1s[col0]     : 0.0f;
                const float bb1 = isA ? b1s[col0 + 1] : 0.0f;
                float* dst = isA ? g_A : g_B;
                const int  cc  = isA ? col0 : (col0 - 128);
                if (n0 < n_nodes) {
                    float2 v = make_float2(acc[im][in][0] + bb0, acc[im][in][1] + bb1);
                    *(float2*)(dst + (size_t)n0 * F + cc) = v;
                }
                if (n1 < n_nodes) {
                    float2 v = make_float2(acc[im][in][2] + bb0, acc[im][in][3] + bb1);
                    *(float2*)(dst + (size_t)n1 * F + cc) = v;
                }
            }
        }
    }
}

// ===========================================================================
// Edge kernel: x = relu(A[src]+B[dst]); D = x @ W2^T; out = relu(D+b2)@W3 + b3
// 128 edges per block, 256 threads (8 warps, each 32m x 64n, K=128)
// smem: Xs[128][PAD], Ws[128][PAD] (W2 transposed), b2s/w3s/esum[128]
// ===========================================================================
#define EDGE_SMEM_U32  (128 * PAD * 2 + 128 * 3)
#define EDGE_SMEM_B    (EDGE_SMEM_U32 * 4)

__global__ void __launch_bounds__(256, 1)
edge_mma_kernel(const int*   __restrict__ src,
                const int*   __restrict__ dst,
                const float* __restrict__ W2,
                const float* __restrict__ b2,
                const float* __restrict__ W3,
                const float* __restrict__ b3,
                float*       __restrict__ out,
                int n_edges)
{
    extern __shared__ uint32_t sm[];
    uint32_t* Xs   = sm;                         // 128*PAD
    uint32_t* Ws   = sm + 128 * PAD;             // 128*PAD
    float*    b2s  = (float*)(sm + 2 * 128 * PAD);
    float*    w3s  = b2s + 128;
    float*    esum = w3s + 128;

    const int tid  = threadIdx.x;
    const int lane = tid & 31;
    const int warp = tid >> 5;
    const int g    = lane >> 2;
    const int t    = lane & 3;
    const int base = blockIdx.x * 128;

    if (tid < 128) {
        b2s[tid]  = b2[tid];
        w3s[tid]  = W3[tid];
        esum[tid] = b3[0];
    }

    // stage W2 transposed: Ws[k][n] = W2[n][k]; thread: n = tid&127, kh = tid>>7
    {
        const int n  = tid & 127;
        const int kh = tid >> 7;
        const float4* wrow = (const float4*)(W2 + (size_t)n * F) + kh * 16;
        #pragma unroll
        for (int q = 0; q < 16; q++) {
            float4 w = __ldg(wrow + q);
            const int k = kh * 64 + q * 4;
            Ws[(k + 0) * PAD + n] = f2tf32(w.x);
            Ws[(k + 1) * PAD + n] = f2tf32(w.y);
            Ws[(k + 2) * PAD + n] = f2tf32(w.z);
            Ws[(k + 3) * PAD + n] = f2tf32(w.w);
        }
    }

    // gather + relu into Xs: row r, half hh
    {
        const int r  = tid >> 1;
        const int hh = tid & 1;
        const int e  = base + r;
        const bool ok = (e < n_edges);
        const float4* ar = nullptr;
        const float4* br = nullptr;
        if (ok) {
            const int s = __ldg(&src[e]);
            const int d = __ldg(&dst[e]);
            ar = (const float4*)(g_A + (size_t)s * F) + hh * 16;
            br = (const float4*)(g_B + (size_t)d * F) + hh * 16;
        }
        #pragma unroll
        for (int q = 0; q < 16; q++) {
            uint32_t x0 = 0, x1 = 0, x2 = 0, x3 = 0;
            if (ok) {
                float4 a = __ldg(ar + q);
                float4 b = __ldg(br + q);
                x0 = f2tf32(fmaxf(a.x + b.x, 0.0f));
                x1 = f2tf32(fmaxf(a.y + b.y, 0.0f));
                x2 = f2tf32(fmaxf(a.z + b.z, 0.0f));
                x3 = f2tf32(fmaxf(a.w + b.w, 0.0f));
            }
            uint32_t* p = &Xs[r * PAD + hh * 64 + q * 4];
            p[0] = x0; p[1] = x1; p[2] = x2; p[3] = x3;
        }
    }
    __syncthreads();

    const int mq = warp & 3;
    const int nh = warp >> 2;
    const int m0 = mq * 32;
    const int nb = nh * 64;

    float acc[2][8][4];
    #pragma unroll
    for (int im = 0; im < 2; im++)
        #pragma unroll
        for (int in = 0; in < 8; in++)
            #pragma unroll
            for (int c = 0; c < 4; c++) acc[im][in][c] = 0.0f;

    #pragma unroll
    for (int k8 = 0; k8 < 16; k8++) {
        const int kc = k8 * 8;
        uint32_t af[2][4];
        #pragma unroll
        for (int im = 0; im < 2; im++) {
            const int r = m0 + im * 16 + g;
            af[im][0] = Xs[(r)     * PAD + kc + t];
            af[im][1] = Xs[(r + 8) * PAD + kc + t];
            af[im][2] = Xs[(r)     * PAD + kc + t + 4];
            af[im][3] = Xs[(r + 8) * PAD + kc + t + 4];
        }
        #pragma unroll
        for (int in = 0; in < 8; in++) {
            const int nc = nb + in * 8 + g;
            uint32_t b0 = Ws[(kc + t)     * PAD + nc];
            uint32_t b1r = Ws[(kc + t + 4) * PAD + nc];
            #pragma unroll
            for (int im = 0; im < 2; im++)
                mma_tf32(acc[im][in][0], acc[im][in][1], acc[im][in][2], acc[im][in][3],
                         af[im][0], af[im][1], af[im][2], af[im][3], b0, b1r);
        }
    }

    // fold: relu(D + b2) * W3, reduce over this warp's 64 cols, atomically
    // combine the two n-half warps per edge in smem.
    #pragma unroll
    for (int im = 0; im < 2; im++) {
        float p0 = 0.0f, p1 = 0.0f;
        #pragma unroll
        for (int in = 0; in < 8; in++) {
            const int col0 = nb + in * 8 + 2 * t;
            const int col1 = col0 + 1;
            const float bb0 = b2s[col0], bb1 = b2s[col1];
            const float w0  = w3s[col0], w1  = w3s[col1];
            p0 = fmaf(fmaxf(acc[im][in][0] + bb0, 0.0f), w0, p0);
            p0 = fmaf(fmaxf(acc[im][in][1] + bb1, 0.0f), w1, p0);
            p1 = fmaf(fmaxf(acc[im][in][2] + bb0, 0.0f), w0, p1);
            p1 = fmaf(fmaxf(acc[im][in][3] + bb1, 0.0f), w1, p1);
        }
        p0 += __shfl_xor_sync(0xFFFFFFFFu, p0, 1);
        p0 += __shfl_xor_sync(0xFFFFFFFFu, p0, 2);
        p1 += __shfl_xor_sync(0xFFFFFFFFu, p1, 1);
        p1 += __shfl_xor_sync(0xFFFFFFFFu, p1, 2);
        if (t == 0) {
            atomicAdd(&esum[m0 + im * 16 + g],     p0);
            atomicAdd(&esum[m0 + im * 16 + g + 8], p1);
        }
    }
    __syncthreads();

    if (tid < 128) {
        const int e = base + tid;
        if (e < n_edges) out[e] = esum[tid];
    }
}

// ===========================================================================
// launch: inputs: h, src, dst, W1, b1, W2, b2, W3, b3 ; out: [n_edges] f32
// ===========================================================================
extern "C" void kernel_launch(void* const* d_in, const int* in_sizes, int n_in,
                              void* d_out, int out_size)
{
    const float* h   = (const float*)d_in[0];
    const int*   src = (const int*)  d_in[1];
    const int*   dst = (const int*)  d_in[2];
    const float* W1  = (const float*)d_in[3];
    const float* b1  = (const float*)d_in[4];
    const float* W2  = (const float*)d_in[5];
    const float* b2  = (const float*)d_in[6];
    const float* W3  = (const float*)d_in[7];
    const float* b3  = (const float*)d_in[8];
    float*       out = (float*)d_out;

    const int n_nodes = in_sizes[0] / F;
    const int n_edges = in_sizes[1];

    cudaFuncSetAttribute(node_mma_kernel,
                         cudaFuncAttributeMaxDynamicSharedMemorySize, NODE_SMEM_B);
    cudaFuncSetAttribute(edge_mma_kernel,
                         cudaFuncAttributeMaxDynamicSharedMemorySize, EDGE_SMEM_B);

    const int gridA = (n_nodes + 127) / 128;
    node_mma_kernel<<<gridA, 256, NODE_SMEM_B>>>(h, W1, b1, n_nodes);

    const int gridB = (n_edges + 127) / 128;
    edge_mma_kernel<<<gridB, 256, EDGE_SMEM_B>>>(src, dst, W2, b2, W3, b3, out, n_edges);
}

// round 5
// speedup vs baseline: 3.5424x; 1.6380x over previous
#include <cuda_runtime.h>
#include <cuda_bf16.h>
#include <cstdint>

#define NN_MAX   100000
#define F        128
#define PAD      136      // node-kernel smem pitch (unchanged, R3)
#define W1PAD    264

// Scratch: A[n][j] = W1[:, :128] @ h[n] + b1 ; B[n][j] = W1[:, 128:] @ h[n]
__device__ float g_A[NN_MAX * F];
__device__ float g_B[NN_MAX * F];

// W2 in mma-fragment order: [ni 0..15][ki 0..15][lane 0..31] -> uint2 {b0,b1}
//   n = ni*8 + (lane>>2),  b0 = tf32(W2[n][ki*8 + (lane&3)]), b1 = ... +4
__device__ uint2 g_W2f[16 * 16 * 32];

// ---------------------------------------------------------------------------
__device__ __forceinline__ uint32_t f2tf32(float f) {
    uint32_t r;
    asm("cvt.rna.tf32.f32 %0, %1;" : "=r"(r) : "f"(f));
    return r;
}

__device__ __forceinline__ void mma_tf32(float& c0, float& c1, float& c2, float& c3,
                                         uint32_t a0, uint32_t a1, uint32_t a2, uint32_t a3,
                                         uint32_t b0, uint32_t b1)
{
    asm volatile(
        "mma.sync.aligned.m16n8k8.row.col.f32.tf32.tf32.f32 "
        "{%0,%1,%2,%3}, {%4,%5,%6,%7}, {%8,%9}, {%0,%1,%2,%3};\n"
        : "+f"(c0), "+f"(c1), "+f"(c2), "+f"(c3)
        : "r"(a0), "r"(a1), "r"(a2), "r"(a3), "r"(b0), "r"(b1));
}

// ===========================================================================
// Prep: pack W2 into fragment order (one tiny launch)
// ===========================================================================
__global__ void pack_w2_kernel(const float* __restrict__ W2)
{
    const int idx  = blockIdx.x * blockDim.x + threadIdx.x;   // 0..8191
    if (idx >= 16 * 16 * 32) return;
    const int lane = idx & 31;
    const int ki   = (idx >> 5) & 15;
    const int ni   = idx >> 9;
    const int g    = lane >> 2;
    const int t    = lane & 3;
    const float* w = W2 + (size_t)(ni * 8 + g) * F + ki * 8;
    uint2 v;
    v.x = f2tf32(__ldg(&w[t]));
    v.y = f2tf32(__ldg(&w[t + 4]));
    g_W2f[idx] = v;
}

// ===========================================================================
// Node kernel (unchanged from R3): [A|B] = h @ W1^T
// ===========================================================================
#define NODE_SMEM_U32  (128 * PAD + 128 * W1PAD + 128)
#define NODE_SMEM_B    (NODE_SMEM_U32 * 4)

__global__ void __launch_bounds__(256, 1)
node_mma_kernel(const float* __restrict__ h,
                const float* __restrict__ W1,
                const float* __restrict__ b1,
                int n_nodes)
{
    extern __shared__ uint32_t sm[];
    uint32_t* Hs  = sm;
    uint32_t* W1s = sm + 128 * PAD;
    float*    b1s = (float*)(sm + 128 * PAD + 128 * W1PAD);

    const int tid  = threadIdx.x;
    const int lane = tid & 31;
    const int warp = tid >> 5;
    const int g    = lane >> 2;
    const int t    = lane & 3;
    const int base = blockIdx.x * 128;

    if (tid < 128) b1s[tid] = b1[tid];

    {
        const int j2 = tid;
        const float* wrow = W1 + (size_t)(j2 & 127) * 256 + ((j2 >> 7) << 7);
        #pragma unroll
        for (int k4 = 0; k4 < 32; k4++) {
            float4 w = __ldg((const float4*)wrow + k4);
            int k = k4 * 4;
            W1s[(k + 0) * W1PAD + j2] = f2tf32(w.x);
            W1s[(k + 1) * W1PAD + j2] = f2tf32(w.y);
            W1s[(k + 2) * W1PAD + j2] = f2tf32(w.z);
            W1s[(k + 3) * W1PAD + j2] = f2tf32(w.w);
        }
    }

    {
        const int r  = tid >> 1;
        const int hh = tid & 1;
        const int n  = base + r;
        const bool ok = (n < n_nodes);
        const float4* hr = (const float4*)(h + (size_t)n * F) + hh * 16;
        #pragma unroll
        for (int q = 0; q < 16; q++) {
            uint32_t x0 = 0, x1 = 0, x2 = 0, x3 = 0;
            if (ok) {
                float4 v = __ldg(hr + q);
                x0 = f2tf32(v.x); x1 = f2tf32(v.y);
                x2 = f2tf32(v.z); x3 = f2tf32(v.w);
            }
            uint32_t* p = &Hs[r * PAD + hh * 64 + q * 4];
            p[0] = x0; p[1] = x1; p[2] = x2; p[3] = x3;
        }
    }
    __syncthreads();

    const int mq = warp & 3;
    const int m0 = mq * 32;

    for (int np = (warp >> 2); np < 4; np += 2) {
        const int nb = np * 64;
        float acc[2][8][4];
        #pragma unroll
        for (int im = 0; im < 2; im++)
            #pragma unroll
            for (int in = 0; in < 8; in++)
                #pragma unroll
                for (int c = 0; c < 4; c++) acc[im][in][c] = 0.0f;

        #pragma unroll
        for (int k8 = 0; k8 < 16; k8++) {
            const int kc = k8 * 8;
            uint32_t af[2][4];
            #pragma unroll
            for (int im = 0; im < 2; im++) {
                const int r = m0 + im * 16 + g;
                af[im][0] = Hs[(r)     * PAD + kc + t];
                af[im][1] = Hs[(r + 8) * PAD + kc + t];
                af[im][2] = Hs[(r)     * PAD + kc + t + 4];
                af[im][3] = Hs[(r + 8) * PAD + kc + t + 4];
            }
            #pragma unroll
            for (int in = 0; in < 8; in++) {
                const int nc = nb + in * 8 + g;
                uint32_t b0  = W1s[(kc + t)     * W1PAD + nc];
                uint32_t b1r = W1s[(kc + t + 4) * W1PAD + nc];
                #pragma unroll
                for (int im = 0; im < 2; im++)
                    mma_tf32(acc[im][in][0], acc[im][in][1], acc[im][in][2], acc[im][in][3],
                             af[im][0], af[im][1], af[im][2], af[im][3], b0, b1r);
            }
        }

        #pragma unroll
        for (int im = 0; im < 2; im++) {
            const int r0 = m0 + im * 16 + g;
            const int n0 = base + r0;
            const int n1 = n0 + 8;
            #pragma unroll
            for (int in = 0; in < 8; in++) {
                const int col0 = nb + in * 8 + 2 * t;
                const bool isA = (col0 < 128);
                const float bb0 = isA ? b1s[col0]     : 0.0f;
                const float bb1 = isA ? b1s[col0 + 1] : 0.0f;
                float* dst = isA ? g_A : g_B;
                const int  cc  = isA ? col0 : (col0 - 128);
                if (n0 < n_nodes) {
                    float2 v = make_float2(acc[im][in][0] + bb0, acc[im][in][1] + bb1);
                    *(float2*)(dst + (size_t)n0 * F + cc) = v;
                }
                if (n1 < n_nodes) {
                    float2 v = make_float2(acc[im][in][2] + bb0, acc[im][in][3] + bb1);
                    *(float2*)(dst + (size_t)n1 * F + cc) = v;
                }
            }
        }
    }
}

// ===========================================================================
// Edge kernel v2: fragment-layout X smem + LDG B fragments.
// Block = 128 edges, 256 threads, 2 blocks/SM.
//   XsF tile (mi,ki): 32 lanes x uint4 quad, tile stride 528 B
//   quad(lane=(g,t)) = { x[mi*16+g][ki*8+t],   x[mi*16+8+g][ki*8+t],
//                        x[mi*16+g][ki*8+t+4], x[mi*16+8+g][ki*8+t+4] }
// ===========================================================================
#define XSF_WORDS   (128 * 132)
#define EDGE_SMEM_B ((XSF_WORDS + 128 * 5) * 4 + 16)

__global__ void __launch_bounds__(256, 2)
edge_mma_kernel(const int*   __restrict__ src,
                const int*   __restrict__ dst,
                const float* __restrict__ b2,
                const float* __restrict__ W3,
                const float* __restrict__ b3,
                float*       __restrict__ out,
                int n_edges)
{
    extern __shared__ uint32_t sm[];
    uint32_t* XsF  = sm;
    int*      ss   = (int*)(sm + XSF_WORDS);
    int*      ds   = ss + 128;
    float*    b2s  = (float*)(ds + 128);
    float*    w3s  = b2s + 128;
    float*    esum = w3s + 128;

    const int tid  = threadIdx.x;
    const int lane = tid & 31;
    const int warp = tid >> 5;
    const int g    = lane >> 2;
    const int t    = lane & 3;
    const int base = blockIdx.x * 128;

    if (tid < 128) {
        const int e = base + tid;
        const bool ok = (e < n_edges);
        ss[tid]   = ok ? __ldg(&src[e]) : 0;
        ds[tid]   = ok ? __ldg(&dst[e]) : 0;
        b2s[tid]  = __ldg(&b2[tid]);
        w3s[tid]  = __ldg(&W3[tid]);
        esum[tid] = __ldg(&b3[0]);
    }
    __syncthreads();

    // ---- producer: gather + relu -> fragment layout ----
    #pragma unroll
    for (int p = 0; p < 4; p++) {
        const int tile = p * 32 + warp * 4 + (lane & 3);
        const int gg   = lane >> 2;                  // fragment row group
        const int mi   = tile >> 4;
        const int ki   = tile & 15;
        const int rA   = mi * 16 + gg;
        const int rB   = rA + 8;
        const float mA = ((base + rA) < n_edges) ? 1.0f : 0.0f;
        const float mB = ((base + rB) < n_edges) ? 1.0f : 0.0f;

        float xA[8], xB[8];
        {
            const float4* pa = (const float4*)(g_A + (size_t)ss[rA] * F + ki * 8);
            const float4* pb = (const float4*)(g_B + (size_t)ds[rA] * F + ki * 8);
            float4 a0 = __ldg(pa), a1 = __ldg(pa + 1);
            float4 c0 = __ldg(pb), c1 = __ldg(pb + 1);
            xA[0] = fmaxf(a0.x + c0.x, 0.f) * mA; xA[1] = fmaxf(a0.y + c0.y, 0.f) * mA;
            xA[2] = fmaxf(a0.z + c0.z, 0.f) * mA; xA[3] = fmaxf(a0.w + c0.w, 0.f) * mA;
            xA[4] = fmaxf(a1.x + c1.x, 0.f) * mA; xA[5] = fmaxf(a1.y + c1.y, 0.f) * mA;
            xA[6] = fmaxf(a1.z + c1.z, 0.f) * mA; xA[7] = fmaxf(a1.w + c1.w, 0.f) * mA;
        }
        {
            const float4* pa = (const float4*)(g_A + (size_t)ss[rB] * F + ki * 8);
            const float4* pb = (const float4*)(g_B + (size_t)ds[rB] * F + ki * 8);
            float4 a0 = __ldg(pa), a1 = __ldg(pa + 1);
            float4 c0 = __ldg(pb), c1 = __ldg(pb + 1);
            xB[0] = fmaxf(a0.x + c0.x, 0.f) * mB; xB[1] = fmaxf(a0.y + c0.y, 0.f) * mB;
            xB[2] = fmaxf(a0.z + c0.z, 0.f) * mB; xB[3] = fmaxf(a0.w + c0.w, 0.f) * mB;
            xB[4] = fmaxf(a1.x + c1.x, 0.f) * mB; xB[5] = fmaxf(a1.y + c1.y, 0.f) * mB;
            xB[6] = fmaxf(a1.z + c1.z, 0.f) * mB; xB[7] = fmaxf(a1.w + c1.w, 0.f) * mB;
        }

        char* tb = (char*)XsF + (size_t)tile * 528 + gg * 64;
        #pragma unroll
        for (int j = 0; j < 4; j++) {
            uint4 q;
            q.x = f2tf32(xA[j]);     q.y = f2tf32(xB[j]);
            q.z = f2tf32(xA[j + 4]); q.w = f2tf32(xB[j + 4]);
            *(uint4*)(tb + j * 16) = q;
        }
    }
    __syncthreads();

    // ---- consumer: warp (mq, nh) = 32m x 64n, K = 128 ----
    const int mq = warp & 3;
    const int nh = warp >> 2;

    float acc[2][8][4];
    #pragma unroll
    for (int im = 0; im < 2; im++)
        #pragma unroll
        for (int in = 0; in < 8; in++)
            #pragma unroll
            for (int c = 0; c < 4; c++) acc[im][in][c] = 0.0f;

    #pragma unroll
    for (int ki = 0; ki < 16; ki++) {
        uint2 bf[8];
        #pragma unroll
        for (int in = 0; in < 8; in++)
            bf[in] = __ldg(&g_W2f[(((nh * 8 + in) << 4) + ki) * 32 + lane]);

        uint4 aq0 = *(const uint4*)((const char*)XsF +
                     (size_t)(((mq * 2 + 0) * 16 + ki)) * 528 + lane * 16);
        uint4 aq1 = *(const uint4*)((const char*)XsF +
                     (size_t)(((mq * 2 + 1) * 16 + ki)) * 528 + lane * 16);

        #pragma unroll
        for (int in = 0; in < 8; in++) {
            mma_tf32(acc[0][in][0], acc[0][in][1], acc[0][in][2], acc[0][in][3],
                     aq0.x, aq0.y, aq0.z, aq0.w, bf[in].x, bf[in].y);
            mma_tf32(acc[1][in][0], acc[1][in][1], acc[1][in][2], acc[1][in][3],
                     aq1.x, aq1.y, aq1.z, aq1.w, bf[in].x, bf[in].y);
        }
    }

    // ---- epilogue: relu(D+b2)*W3, reduce 64 cols per warp, combine in smem ----
    #pragma unroll
    for (int im = 0; im < 2; im++) {
        float p0 = 0.0f, p1 = 0.0f;
        #pragma unroll
        for (int in = 0; in < 8; in++) {
            const int col0 = nh * 64 + in * 8 + 2 * t;
            const float bb0 = b2s[col0], bb1 = b2s[col0 + 1];
            const float w0  = w3s[col0], w1  = w3s[col0 + 1];
            p0 = fmaf(fmaxf(acc[im][in][0] + bb0, 0.f), w0, p0);
            p0 = fmaf(fmaxf(acc[im][in][1] + bb1, 0.f), w1, p0);
            p1 = fmaf(fmaxf(acc[im][in][2] + bb0, 0.f), w0, p1);
            p1 = fmaf(fmaxf(acc[im][in][3] + bb1, 0.f), w1, p1);
        }
        p0 += __shfl_xor_sync(0xFFFFFFFFu, p0, 1);
        p0 += __shfl_xor_sync(0xFFFFFFFFu, p0, 2);
        p1 += __shfl_xor_sync(0xFFFFFFFFu, p1, 1);
        p1 += __shfl_xor_sync(0xFFFFFFFFu, p1, 2);
        if (t == 0) {
            atomicAdd(&esum[mq * 32 + im * 16 + g],     p0);
            atomicAdd(&esum[mq * 32 + im * 16 + g + 8], p1);
        }
    }
    __syncthreads();

    if (tid < 128) {
        const int e = base + tid;
        if (e < n_edges) out[e] = esum[tid];
    }
}

// ===========================================================================
// launch: inputs: h, src, dst, W1, b1, W2, b2, W3, b3 ; out: [n_edges] f32
// ===========================================================================
extern "C" void kernel_launch(void* const* d_in, const int* in_sizes, int n_in,
                              void* d_out, int out_size)
{
    const float* h   = (const float*)d_in[0];
    const int*   src = (const int*)  d_in[1];
    const int*   dst = (const int*)  d_in[2];
    const float* W1  = (const float*)d_in[3];
    const float* b1  = (const float*)d_in[4];
    const float* W2  = (const float*)d_in[5];
    const float* b2  = (const float*)d_in[6];
    const float* W3  = (const float*)d_in[7];
    const float* b3  = (const float*)d_in[8];
    float*       out = (float*)d_out;

    const int n_nodes = in_sizes[0] / F;
    const int n_edges = in_sizes[1];

    cudaFuncSetAttribute(node_mma_kernel,
                         cudaFuncAttributeMaxDynamicSharedMemorySize, NODE_SMEM_B);
    cudaFuncSetAttribute(edge_mma_kernel,
                         cudaFuncAttributeMaxDynamicSharedMemorySize, EDGE_SMEM_B);

    pack_w2_kernel<<<32, 256>>>(W2);

    const int gridA = (n_nodes + 127) / 128;
    node_mma_kernel<<<gridA, 256, NODE_SMEM_B>>>(h, W1, b1, n_nodes);

    const int gridB = (n_edges + 127) / 128;
    edge_mma_kernel<<<gridB, 256, EDGE_SMEM_B>>>(src, dst, b2, W3, b3, out, n_edges);
}

// round 6
// speedup vs baseline: 4.5567x; 1.2863x over previous
#include <cuda_runtime.h>
#include <cuda_bf16.h>
#include <cstdint>

#define NN_MAX   100000
#define F        128

// Scratch: A[n][j] = W1[:, :128] @ h[n] + b1 ; B[n][j] = W1[:, 128:] @ h[n]
__device__ float g_A[NN_MAX * F];
__device__ float g_B[NN_MAX * F];

// W2 fragments: [ni 0..15][ki 0..15][lane] -> uint2 {b0,b1}
__device__ uint2 g_W2f[16 * 16 * 32];
// W1 fragments (256 output cols = A||B): [ni 0..31][ki 0..15][lane] -> uint2
//   j2 = ni*8 + (lane>>2); source = W1[j2&127][(j2>>7)*128 + ki*8 + (lane&3) (+4)]
__device__ uint2 g_W1f[32 * 16 * 32];

// ---------------------------------------------------------------------------
__device__ __forceinline__ uint32_t f2tf32(float f) {
    uint32_t r;
    asm("cvt.rna.tf32.f32 %0, %1;" : "=r"(r) : "f"(f));
    return r;
}

__device__ __forceinline__ void mma_tf32(float& c0, float& c1, float& c2, float& c3,
                                         uint32_t a0, uint32_t a1, uint32_t a2, uint32_t a3,
                                         uint32_t b0, uint32_t b1)
{
    asm volatile(
        "mma.sync.aligned.m16n8k8.row.col.f32.tf32.tf32.f32 "
        "{%0,%1,%2,%3}, {%4,%5,%6,%7}, {%8,%9}, {%0,%1,%2,%3};\n"
        : "+f"(c0), "+f"(c1), "+f"(c2), "+f"(c3)
        : "r"(a0), "r"(a1), "r"(a2), "r"(a3), "r"(b0), "r"(b1));
}

// ===========================================================================
// Prep kernels: pack W2 / W1 into fragment order
// ===========================================================================
__global__ void pack_w2_kernel(const float* __restrict__ W2)
{
    const int idx  = blockIdx.x * blockDim.x + threadIdx.x;
    if (idx >= 16 * 16 * 32) return;
    const int lane = idx & 31;
    const int ki   = (idx >> 5) & 15;
    const int ni   = idx >> 9;
    const int g    = lane >> 2;
    const int t    = lane & 3;
    const float* w = W2 + (size_t)(ni * 8 + g) * F + ki * 8;
    uint2 v;
    v.x = f2tf32(__ldg(&w[t]));
    v.y = f2tf32(__ldg(&w[t + 4]));
    g_W2f[idx] = v;
}

__global__ void pack_w1_kernel(const float* __restrict__ W1)
{
    const int idx  = blockIdx.x * blockDim.x + threadIdx.x;
    if (idx >= 32 * 16 * 32) return;
    const int lane = idx & 31;
    const int ki   = (idx >> 5) & 15;
    const int ni   = idx >> 9;
    const int g    = lane >> 2;
    const int t    = lane & 3;
    const int j2   = ni * 8 + g;                   // output col 0..255
    const float* w = W1 + (size_t)(j2 & 127) * 256 + ((j2 >> 7) << 7) + ki * 8;
    uint2 v;
    v.x = f2tf32(__ldg(&w[t]));
    v.y = f2tf32(__ldg(&w[t + 4]));
    g_W1f[idx] = v;
}

// ===========================================================================
// Shared fragment-tile layout (both kernels):
//   tile = mi*16 + ki (mi 0..7, ki 0..15), stride 528 B; lane quad uint4 =
//   { x[mi*16+g][ki*8+t], x[mi*16+8+g][ki*8+t],
//     x[mi*16+g][ki*8+t+4], x[mi*16+8+g][ki*8+t+4] }
// ===========================================================================
#define XSF_WORDS   (128 * 132)

// ===========================================================================
// Node kernel v2: [A|B] = h @ W1^T, fragment smem + global W1 fragments.
// 128 nodes / block, 256 threads, 2 blocks/SM.
// ===========================================================================
#define NODE_SMEM_B ((XSF_WORDS + 128) * 4 + 16)

__global__ void __launch_bounds__(256, 2)
node_mma_kernel(const float* __restrict__ h,
                const float* __restrict__ b1,
                int n_nodes)
{
    extern __shared__ uint32_t sm[];
    uint32_t* HsF = sm;
    float*    b1s = (float*)(sm + XSF_WORDS);

    const int tid  = threadIdx.x;
    const int lane = tid & 31;
    const int warp = tid >> 5;
    const int g    = lane >> 2;
    const int t    = lane & 3;
    const int base = blockIdx.x * 128;

    if (tid < 128) b1s[tid] = __ldg(&b1[tid]);

    // producer: h -> fragment layout
    #pragma unroll
    for (int p = 0; p < 4; p++) {
        const int tile = p * 32 + warp * 4 + (lane & 3);
        const int gg   = lane >> 2;
        const int mi   = tile >> 4;
        const int ki   = tile & 15;
        const int rA   = mi * 16 + gg;
        const int rB   = rA + 8;
        const float mA = ((base + rA) < n_nodes) ? 1.0f : 0.0f;
        const float mB = ((base + rB) < n_nodes) ? 1.0f : 0.0f;
        const int  nA  = ((base + rA) < n_nodes) ? (base + rA) : 0;
        const int  nB  = ((base + rB) < n_nodes) ? (base + rB) : 0;

        const float4* pa = (const float4*)(h + (size_t)nA * F + ki * 8);
        const float4* pb = (const float4*)(h + (size_t)nB * F + ki * 8);
        float4 a0 = __ldg(pa), a1 = __ldg(pa + 1);
        float4 c0 = __ldg(pb), c1 = __ldg(pb + 1);

        float xA[8], xB[8];
        xA[0] = a0.x * mA; xA[1] = a0.y * mA; xA[2] = a0.z * mA; xA[3] = a0.w * mA;
        xA[4] = a1.x * mA; xA[5] = a1.y * mA; xA[6] = a1.z * mA; xA[7] = a1.w * mA;
        xB[0] = c0.x * mB; xB[1] = c0.y * mB; xB[2] = c0.z * mB; xB[3] = c0.w * mB;
        xB[4] = c1.x * mB; xB[5] = c1.y * mB; xB[6] = c1.z * mB; xB[7] = c1.w * mB;

        char* tb = (char*)HsF + (size_t)tile * 528 + gg * 64;
        #pragma unroll
        for (int j = 0; j < 4; j++) {
            uint4 q;
            q.x = f2tf32(xA[j]);     q.y = f2tf32(xB[j]);
            q.z = f2tf32(xA[j + 4]); q.w = f2tf32(xB[j + 4]);
            *(uint4*)(tb + j * 16) = q;
        }
    }
    __syncthreads();

    const int mq = warp & 3;

    // each warp: rows [mq*32, mq*32+32), two 64-col tiles np, np+2
    for (int np = (warp >> 2); np < 4; np += 2) {
        float acc[2][8][4];
        #pragma unroll
        for (int im = 0; im < 2; im++)
            #pragma unroll
            for (int in = 0; in < 8; in++)
                #pragma unroll
                for (int c = 0; c < 4; c++) acc[im][in][c] = 0.0f;

        #pragma unroll
        for (int ki = 0; ki < 16; ki++) {
            uint2 bf[8];
            #pragma unroll
            for (int in = 0; in < 8; in++)
                bf[in] = __ldg(&g_W1f[(((np * 8 + in) << 4) + ki) * 32 + lane]);

            uint4 aq0 = *(const uint4*)((const char*)HsF +
                         (size_t)((mq * 2 + 0) * 16 + ki) * 528 + lane * 16);
            uint4 aq1 = *(const uint4*)((const char*)HsF +
                         (size_t)((mq * 2 + 1) * 16 + ki) * 528 + lane * 16);

            #pragma unroll
            for (int in = 0; in < 8; in++) {
                mma_tf32(acc[0][in][0], acc[0][in][1], acc[0][in][2], acc[0][in][3],
                         aq0.x, aq0.y, aq0.z, aq0.w, bf[in].x, bf[in].y);
                mma_tf32(acc[1][in][0], acc[1][in][1], acc[1][in][2], acc[1][in][3],
                         aq1.x, aq1.y, aq1.z, aq1.w, bf[in].x, bf[in].y);
            }
        }

        // epilogue: write A (cols<128, +b1) / B (cols>=128)
        const int nb = np * 64;
        #pragma unroll
        for (int im = 0; im < 2; im++) {
            const int r0 = mq * 32 + im * 16 + g;
            const int n0 = base + r0;
            const int n1 = n0 + 8;
            #pragma unroll
            for (int in = 0; in < 8; in++) {
                const int col0 = nb + in * 8 + 2 * t;
                const bool isA = (col0 < 128);
                const float bb0 = isA ? b1s[col0]     : 0.0f;
                const float bb1 = isA ? b1s[col0 + 1] : 0.0f;
                float* dst = isA ? g_A : g_B;
                const int  cc  = isA ? col0 : (col0 - 128);
                if (n0 < n_nodes) {
                    float2 v = make_float2(acc[im][in][0] + bb0, acc[im][in][1] + bb1);
                    *(float2*)(dst + (size_t)n0 * F + cc) = v;
                }
                if (n1 < n_nodes) {
                    float2 v = make_float2(acc[im][in][2] + bb0, acc[im][in][3] + bb1);
                    *(float2*)(dst + (size_t)n1 * F + cc) = v;
                }
            }
        }
    }
}

// ===========================================================================
// Edge kernel (unchanged from R5): fragment smem X + global W2 fragments
// ===========================================================================
#define EDGE_SMEM_B ((XSF_WORDS + 128 * 5) * 4 + 16)

__global__ void __launch_bounds__(256, 2)
edge_mma_kernel(const int*   __restrict__ src,
                const int*   __restrict__ dst,
                const float* __restrict__ b2,
                const float* __restrict__ W3,
                const float* __restrict__ b3,
                float*       __restrict__ out,
                int n_edges)
{
    extern __shared__ uint32_t sm[];
    uint32_t* XsF  = sm;
    int*      ss   = (int*)(sm + XSF_WORDS);
    int*      ds   = ss + 128;
    float*    b2s  = (float*)(ds + 128);
    float*    w3s  = b2s + 128;
    float*    esum = w3s + 128;

    const int tid  = threadIdx.x;
    const int lane = tid & 31;
    const int warp = tid >> 5;
    const int g    = lane >> 2;
    const int t    = lane & 3;
    const int base = blockIdx.x * 128;

    if (tid < 128) {
        const int e = base + tid;
        const bool ok = (e < n_edges);
        ss[tid]   = ok ? __ldg(&src[e]) : 0;
        ds[tid]   = ok ? __ldg(&dst[e]) : 0;
        b2s[tid]  = __ldg(&b2[tid]);
        w3s[tid]  = __ldg(&W3[tid]);
        esum[tid] = __ldg(&b3[0]);
    }
    __syncthreads();

    #pragma unroll
    for (int p = 0; p < 4; p++) {
        const int tile = p * 32 + warp * 4 + (lane & 3);
        const int gg   = lane >> 2;
        const int mi   = tile >> 4;
        const int ki   = tile & 15;
        const int rA   = mi * 16 + gg;
        const int rB   = rA + 8;
        const float mA = ((base + rA) < n_edges) ? 1.0f : 0.0f;
        const float mB = ((base + rB) < n_edges) ? 1.0f : 0.0f;

        float xA[8], xB[8];
        {
            const float4* pa = (const float4*)(g_A + (size_t)ss[rA] * F + ki * 8);
            const float4* pb = (const float4*)(g_B + (size_t)ds[rA] * F + ki * 8);
            float4 a0 = __ldg(pa), a1 = __ldg(pa + 1);
            float4 c0 = __ldg(pb), c1 = __ldg(pb + 1);
            xA[0] = fmaxf(a0.x + c0.x, 0.f) * mA; xA[1] = fmaxf(a0.y + c0.y, 0.f) * mA;
            xA[2] = fmaxf(a0.z + c0.z, 0.f) * mA; xA[3] = fmaxf(a0.w + c0.w, 0.f) * mA;
            xA[4] = fmaxf(a1.x + c1.x, 0.f) * mA; xA[5] = fmaxf(a1.y + c1.y, 0.f) * mA;
            xA[6] = fmaxf(a1.z + c1.z, 0.f) * mA; xA[7] = fmaxf(a1.w + c1.w, 0.f) * mA;
        }
        {
            const float4* pa = (const float4*)(g_A + (size_t)ss[rB] * F + ki * 8);
            const float4* pb = (const float4*)(g_B + (size_t)ds[rB] * F + ki * 8);
            float4 a0 = __ldg(pa), a1 = __ldg(pa + 1);
            float4 c0 = __ldg(pb), c1 = __ldg(pb + 1);
            xB[0] = fmaxf(a0.x + c0.x, 0.f) * mB; xB[1] = fmaxf(a0.y + c0.y, 0.f) * mB;
            xB[2] = fmaxf(a0.z + c0.z, 0.f) * mB; xB[3] = fmaxf(a0.w + c0.w, 0.f) * mB;
            xB[4] = fmaxf(a1.x + c1.x, 0.f) * mB; xB[5] = fmaxf(a1.y + c1.y, 0.f) * mB;
            xB[6] = fmaxf(a1.z + c1.z, 0.f) * mB; xB[7] = fmaxf(a1.w + c1.w, 0.f) * mB;
        }

        char* tb = (char*)XsF + (size_t)tile * 528 + gg * 64;
        #pragma unroll
        for (int j = 0; j < 4; j++) {
            uint4 q;
            q.x = f2tf32(xA[j]);     q.y = f2tf32(xB[j]);
            q.z = f2tf32(xA[j + 4]); q.w = f2tf32(xB[j + 4]);
            *(uint4*)(tb + j * 16) = q;
        }
    }
    __syncthreads();

    const int mq = warp & 3;
    const int nh = warp >> 2;

    float acc[2][8][4];
    #pragma unroll
    for (int im = 0; im < 2; im++)
        #pragma unroll
        for (int in = 0; in < 8; in++)
            #pragma unroll
            for (int c = 0; c < 4; c++) acc[im][in][c] = 0.0f;

    #pragma unroll
    for (int ki = 0; ki < 16; ki++) {
        uint2 bf[8];
        #pragma unroll
        for (int in = 0; in < 8; in++)
            bf[in] = __ldg(&g_W2f[(((nh * 8 + in) << 4) + ki) * 32 + lane]);

        uint4 aq0 = *(const uint4*)((const char*)XsF +
                     (size_t)((mq * 2 + 0) * 16 + ki) * 528 + lane * 16);
        uint4 aq1 = *(const uint4*)((const char*)XsF +
                     (size_t)((mq * 2 + 1) * 16 + ki) * 528 + lane * 16);

        #pragma unroll
        for (int in = 0; in < 8; in++) {
            mma_tf32(acc[0][in][0], acc[0][in][1], acc[0][in][2], acc[0][in][3],
                     aq0.x, aq0.y, aq0.z, aq0.w, bf[in].x, bf[in].y);
            mma_tf32(acc[1][in][0], acc[1][in][1], acc[1][in][2], acc[1][in][3],
                     aq1.x, aq1.y, aq1.z, aq1.w, bf[in].x, bf[in].y);
        }
    }

    #pragma unroll
    for (int im = 0; im < 2; im++) {
        float p0 = 0.0f, p1 = 0.0f;
        #pragma unroll
        for (int in = 0; in < 8; in++) {
            const int col0 = nh * 64 + in * 8 + 2 * t;
            const float bb0 = b2s[col0], bb1 = b2s[col0 + 1];
            const float w0  = w3s[col0], w1  = w3s[col0 + 1];
            p0 = fmaf(fmaxf(acc[im][in][0] + bb0, 0.f), w0, p0);
            p0 = fmaf(fmaxf(acc[im][in][1] + bb1, 0.f), w1, p0);
            p1 = fmaf(fmaxf(acc[im][in][2] + bb0, 0.f), w0, p1);
            p1 = fmaf(fmaxf(acc[im][in][3] + bb1, 0.f), w1, p1);
        }
        p0 += __shfl_xor_sync(0xFFFFFFFFu, p0, 1);
        p0 += __shfl_xor_sync(0xFFFFFFFFu, p0, 2);
        p1 += __shfl_xor_sync(0xFFFFFFFFu, p1, 1);
        p1 += __shfl_xor_sync(0xFFFFFFFFu, p1, 2);
        if (t == 0) {
            atomicAdd(&esum[mq * 32 + im * 16 + g],     p0);
            atomicAdd(&esum[mq * 32 + im * 16 + g + 8], p1);
        }
    }
    __syncthreads();

    if (tid < 128) {
        const int e = base + tid;
        if (e < n_edges) out[e] = esum[tid];
    }
}

// ===========================================================================
// launch: inputs: h, src, dst, W1, b1, W2, b2, W3, b3 ; out: [n_edges] f32
// ===========================================================================
extern "C" void kernel_launch(void* const* d_in, const int* in_sizes, int n_in,
                              void* d_out, int out_size)
{
    const float* h   = (const float*)d_in[0];
    const int*   src = (const int*)  d_in[1];
    const int*   dst = (const int*)  d_in[2];
    const float* W1  = (const float*)d_in[3];
    const float* b1  = (const float*)d_in[4];
    const float* W2  = (const float*)d_in[5];
    const float* b2  = (const float*)d_in[6];
    const float* W3  = (const float*)d_in[7];
    const float* b3  = (const float*)d_in[8];
    float*       out = (float*)d_out;

    const int n_nodes = in_sizes[0] / F;
    const int n_edges = in_sizes[1];

    cudaFuncSetAttribute(node_mma_kernel,
                         cudaFuncAttributeMaxDynamicSharedMemorySize, NODE_SMEM_B);
    cudaFuncSetAttribute(edge_mma_kernel,
                         cudaFuncAttributeMaxDynamicSharedMemorySize, EDGE_SMEM_B);

    pack_w2_kernel<<<32, 256>>>(W2);
    pack_w1_kernel<<<64, 256>>>(W1);

    const int gridA = (n_nodes + 127) / 128;
    node_mma_kernel<<<gridA, 256, NODE_SMEM_B>>>(h, b1, n_nodes);

    const int gridB = (n_edges + 127) / 128;
    edge_mma_kernel<<<gridB, 256, EDGE_SMEM_B>>>(src, dst, b2, W3, b3, out, n_edges);
}

// round 7
// speedup vs baseline: 5.5118x; 1.2096x over previous
#include <cuda_runtime.h>
#include <cuda_fp16.h>
#include <cstdint>

#define NN_MAX   100000
#define F        128

// Scratch: A[n][j] = W1[:, :128] @ h[n] + b1 ; B[n][j] = W1[:, 128:] @ h[n]
__device__ float g_A[NN_MAX * F];
__device__ float g_B[NN_MAX * F];

// fp16 b-fragments for m16n8k16 (row.col):
//   b0 = {W[n][kc+2t], W[n][kc+2t+1]}, b1 = {W[n][kc+2t+8], W[n][kc+2t+9]},
//   n = ni*8 + (lane>>2), kc = ki16*16
// W2: [ni 0..15][ki16 0..7][lane] ; W1 (256 outs = A||B): [ni 0..31][ki16 0..7][lane]
__device__ uint2 g_W2f[16 * 8 * 32];
__device__ uint2 g_W1f[32 * 8 * 32];

// ---------------------------------------------------------------------------
__device__ __forceinline__ uint32_t h2pack(float lo, float hi) {
    __half2 h = __floats2half2_rn(lo, hi);     // x = lo (low half), y = hi
    return *reinterpret_cast<uint32_t*>(&h);
}

// D += A*B, m16n8k16 fp16 inputs, fp32 accum (row.col)
__device__ __forceinline__ void mma_f16(float& c0, float& c1, float& c2, float& c3,
                                        uint32_t a0, uint32_t a1, uint32_t a2, uint32_t a3,
                                        uint32_t b0, uint32_t b1)
{
    asm volatile(
        "mma.sync.aligned.m16n8k16.row.col.f32.f16.f16.f32 "
        "{%0,%1,%2,%3}, {%4,%5,%6,%7}, {%8,%9}, {%0,%1,%2,%3};\n"
        : "+f"(c0), "+f"(c1), "+f"(c2), "+f"(c3)
        : "r"(a0), "r"(a1), "r"(a2), "r"(a3), "r"(b0), "r"(b1));
}

// ===========================================================================
// Prep kernels: pack W2 / W1 into fp16 fragment order
// ===========================================================================
__global__ void pack_w2_kernel(const float* __restrict__ W2)
{
    const int idx  = blockIdx.x * blockDim.x + threadIdx.x;   // 0..4095
    if (idx >= 16 * 8 * 32) return;
    const int lane = idx & 31;
    const int ki   = (idx >> 5) & 7;
    const int ni   = idx >> 8;
    const int g    = lane >> 2;
    const int t    = lane & 3;
    const float* w = W2 + (size_t)(ni * 8 + g) * F + ki * 16;
    uint2 v;
    v.x = h2pack(__ldg(&w[2 * t]),     __ldg(&w[2 * t + 1]));
    v.y = h2pack(__ldg(&w[2 * t + 8]), __ldg(&w[2 * t + 9]));
    g_W2f[idx] = v;
}

__global__ void pack_w1_kernel(const float* __restrict__ W1)
{
    const int idx  = blockIdx.x * blockDim.x + threadIdx.x;   // 0..8191
    if (idx >= 32 * 8 * 32) return;
    const int lane = idx & 31;
    const int ki   = (idx >> 5) & 7;
    const int ni   = idx >> 8;
    const int g    = lane >> 2;
    const int t    = lane & 3;
    const int j2   = ni * 8 + g;                   // output col 0..255
    const float* w = W1 + (size_t)(j2 & 127) * 256 + ((j2 >> 7) << 7) + ki * 16;
    uint2 v;
    v.x = h2pack(__ldg(&w[2 * t]),     __ldg(&w[2 * t + 1]));
    v.y = h2pack(__ldg(&w[2 * t + 8]), __ldg(&w[2 * t + 9]));
    g_W1f[idx] = v;
}

// ===========================================================================
// Fragment-tile layout (fp16): tile = mi*8 + ki16 (mi 0..7, ki16 0..7),
// stride 528 B. Consumer lane (g,t) reads uint4 at tile*528 + lane*16:
//   { h2(x[mi*16+g][kc+2t],   x[..][kc+2t+1]),
//     h2(x[mi*16+8+g][kc+2t], x[..][kc+2t+1]),
//     h2(x[mi*16+g][kc+2t+8], x[..][kc+2t+9]),
//     h2(x[mi*16+8+g][kc+2t+8], x[..][kc+2t+9]) },  kc = ki16*16
// ===========================================================================
#define XSF_WORDS   (64 * 132)

// ===========================================================================
// Node kernel: [A|B] = h @ W1^T (fp16 frags). 128 nodes, 256 thr, 2 blk/SM.
// ===========================================================================
#define NODE_SMEM_B ((XSF_WORDS + 128) * 4 + 16)

__global__ void __launch_bounds__(256, 2)
node_mma_kernel(const float* __restrict__ h,
                const float* __restrict__ b1,
                int n_nodes)
{
    extern __shared__ uint32_t sm[];
    uint32_t* HsF = sm;
    float*    b1s = (float*)(sm + XSF_WORDS);

    const int tid  = threadIdx.x;
    const int lane = tid & 31;
    const int warp = tid >> 5;
    const int g    = lane >> 2;
    const int t    = lane & 3;
    const int base = blockIdx.x * 128;

    if (tid < 128) b1s[tid] = __ldg(&b1[tid]);

    // producer: 2 tasks/thread; task = (tile, gg)
    #pragma unroll
    for (int p = 0; p < 2; p++) {
        const int tile = p * 32 + warp * 4 + (lane & 3);   // 0..63
        const int gg   = lane >> 2;
        const int mi   = tile >> 3;
        const int kc   = (tile & 7) * 16;
        const int rA   = mi * 16 + gg;
        const int rB   = rA + 8;
        const float mA = ((base + rA) < n_nodes) ? 1.0f : 0.0f;
        const float mB = ((base + rB) < n_nodes) ? 1.0f : 0.0f;
        const int  nA  = ((base + rA) < n_nodes) ? (base + rA) : 0;
        const int  nB  = ((base + rB) < n_nodes) ? (base + rB) : 0;

        float xA[16], xB[16];
        {
            const float4* pa = (const float4*)(h + (size_t)nA * F + kc);
            const float4* pb = (const float4*)(h + (size_t)nB * F + kc);
            #pragma unroll
            for (int q = 0; q < 4; q++) {
                float4 a = __ldg(pa + q);
                float4 b = __ldg(pb + q);
                xA[q*4+0] = a.x * mA; xA[q*4+1] = a.y * mA;
                xA[q*4+2] = a.z * mA; xA[q*4+3] = a.w * mA;
                xB[q*4+0] = b.x * mB; xB[q*4+1] = b.y * mB;
                xB[q*4+2] = b.z * mB; xB[q*4+3] = b.w * mB;
            }
        }

        char* tb = (char*)HsF + (size_t)tile * 528 + gg * 64;
        #pragma unroll
        for (int j = 0; j < 4; j++) {
            uint4 q;
            q.x = h2pack(xA[2*j],     xA[2*j + 1]);
            q.y = h2pack(xB[2*j],     xB[2*j + 1]);
            q.z = h2pack(xA[2*j + 8], xA[2*j + 9]);
            q.w = h2pack(xB[2*j + 8], xB[2*j + 9]);
            *(uint4*)(tb + j * 16) = q;
        }
    }
    __syncthreads();

    const int mq = warp & 3;

    for (int np = (warp >> 2); np < 4; np += 2) {
        float acc[2][8][4];
        #pragma unroll
        for (int im = 0; im < 2; im++)
            #pragma unroll
            for (int in = 0; in < 8; in++)
                #pragma unroll
                for (int c = 0; c < 4; c++) acc[im][in][c] = 0.0f;

        #pragma unroll
        for (int ki = 0; ki < 8; ki++) {
            uint2 bf[8];
            #pragma unroll
            for (int in = 0; in < 8; in++)
                bf[in] = __ldg(&g_W1f[(((np * 8 + in) << 3) + ki) * 32 + lane]);

            uint4 aq0 = *(const uint4*)((const char*)HsF +
                         (size_t)((mq * 2 + 0) * 8 + ki) * 528 + lane * 16);
            uint4 aq1 = *(const uint4*)((const char*)HsF +
                         (size_t)((mq * 2 + 1) * 8 + ki) * 528 + lane * 16);

            #pragma unroll
            for (int in = 0; in < 8; in++) {
                mma_f16(acc[0][in][0], acc[0][in][1], acc[0][in][2], acc[0][in][3],
                        aq0.x, aq0.y, aq0.z, aq0.w, bf[in].x, bf[in].y);
                mma_f16(acc[1][in][0], acc[1][in][1], acc[1][in][2], acc[1][in][3],
                        aq1.x, aq1.y, aq1.z, aq1.w, bf[in].x, bf[in].y);
            }
        }

        const int nb = np * 64;
        #pragma unroll
        for (int im = 0; im < 2; im++) {
            const int r0 = mq * 32 + im * 16 + g;
            const int n0 = base + r0;
            const int n1 = n0 + 8;
            #pragma unroll
            for (int in = 0; in < 8; in++) {
                const int col0 = nb + in * 8 + 2 * t;
                const bool isA = (col0 < 128);
                const float bb0 = isA ? b1s[col0]     : 0.0f;
                const float bb1 = isA ? b1s[col0 + 1] : 0.0f;
                float* dst = isA ? g_A : g_B;
                const int  cc  = isA ? col0 : (col0 - 128);
                if (n0 < n_nodes) {
                    float2 v = make_float2(acc[im][in][0] + bb0, acc[im][in][1] + bb1);
                    *(float2*)(dst + (size_t)n0 * F + cc) = v;
                }
                if (n1 < n_nodes) {
                    float2 v = make_float2(acc[im][in][2] + bb0, acc[im][in][3] + bb1);
                    *(float2*)(dst + (size_t)n1 * F + cc) = v;
                }
            }
        }
    }
}

// ===========================================================================
// Edge kernel: x = relu(A[src]+B[dst]); D = x @ W2^T (fp16);
// out = relu(D+b2)@W3 + b3. 128 edges, 256 thr, 2 blk/SM.
// ===========================================================================
#define EDGE_SMEM_B ((XSF_WORDS + 128 * 5) * 4 + 16)

__global__ void __launch_bounds__(256, 2)
edge_mma_kernel(const int*   __restrict__ src,
                const int*   __restrict__ dst,
                const float* __restrict__ b2,
                const float* __restrict__ W3,
                const float* __restrict__ b3,
                float*       __restrict__ out,
                int n_edges)
{
    extern __shared__ uint32_t sm[];
    uint32_t* XsF  = sm;
    int*      ss   = (int*)(sm + XSF_WORDS);
    int*      ds   = ss + 128;
    float*    b2s  = (float*)(ds + 128);
    float*    w3s  = b2s + 128;
    float*    esum = w3s + 128;

    const int tid  = threadIdx.x;
    const int lane = tid & 31;
    const int warp = tid >> 5;
    const int g    = lane >> 2;
    const int t    = lane & 3;
    const int base = blockIdx.x * 128;

    if (tid < 128) {
        const int e = base + tid;
        const bool ok = (e < n_edges);
        ss[tid]   = ok ? __ldg(&src[e]) : 0;
        ds[tid]   = ok ? __ldg(&dst[e]) : 0;
        b2s[tid]  = __ldg(&b2[tid]);
        w3s[tid]  = __ldg(&W3[tid]);
        esum[tid] = __ldg(&b3[0]);
    }
    __syncthreads();

    // producer: gather + relu -> fp16 fragment layout (2 tasks/thread)
    #pragma unroll
    for (int p = 0; p < 2; p++) {
        const int tile = p * 32 + warp * 4 + (lane & 3);
        const int gg   = lane >> 2;
        const int mi   = tile >> 3;
        const int kc   = (tile & 7) * 16;
        const int rA   = mi * 16 + gg;
        const int rB   = rA + 8;
        const float mA = ((base + rA) < n_edges) ? 1.0f : 0.0f;
        const float mB = ((base + rB) < n_edges) ? 1.0f : 0.0f;

        float xA[16], xB[16];
        {
            const float4* pa = (const float4*)(g_A + (size_t)ss[rA] * F + kc);
            const float4* pb = (const float4*)(g_B + (size_t)ds[rA] * F + kc);
            #pragma unroll
            for (int q = 0; q < 4; q++) {
                float4 a = __ldg(pa + q);
                float4 b = __ldg(pb + q);
                xA[q*4+0] = fmaxf(a.x + b.x, 0.f) * mA;
                xA[q*4+1] = fmaxf(a.y + b.y, 0.f) * mA;
                xA[q*4+2] = fmaxf(a.z + b.z, 0.f) * mA;
                xA[q*4+3] = fmaxf(a.w + b.w, 0.f) * mA;
            }
        }
        {
            const float4* pa = (const float4*)(g_A + (size_t)ss[rB] * F + kc);
            const float4* pb = (const float4*)(g_B + (size_t)ds[rB] * F + kc);
            #pragma unroll
            for (int q = 0; q < 4; q++) {
                float4 a = __ldg(pa + q);
                float4 b = __ldg(pb + q);
                xB[q*4+0] = fmaxf(a.x + b.x, 0.f) * mB;
                xB[q*4+1] = fmaxf(a.y + b.y, 0.f) * mB;
                xB[q*4+2] = fmaxf(a.z + b.z, 0.f) * mB;
                xB[q*4+3] = fmaxf(a.w + b.w, 0.f) * mB;
            }
        }

        char* tb = (char*)XsF + (size_t)tile * 528 + gg * 64;
        #pragma unroll
        for (int j = 0; j < 4; j++) {
            uint4 q;
            q.x = h2pack(xA[2*j],     xA[2*j + 1]);
            q.y = h2pack(xB[2*j],     xB[2*j + 1]);
            q.z = h2pack(xA[2*j + 8], xA[2*j + 9]);
            q.w = h2pack(xB[2*j + 8], xB[2*j + 9]);
            *(uint4*)(tb + j * 16) = q;
        }
    }
    __syncthreads();

    const int mq = warp & 3;
    const int nh = warp >> 2;

    float acc[2][8][4];
    #pragma unroll
    for (int im = 0; im < 2; im++)
        #pragma unroll
        for (int in = 0; in < 8; in++)
            #pragma unroll
            for (int c = 0; c < 4; c++) acc[im][in][c] = 0.0f;

    #pragma unroll
    for (int ki = 0; ki < 8; ki++) {
        uint2 bf[8];
        #pragma unroll
        for (int in = 0; in < 8; in++)
            bf[in] = __ldg(&g_W2f[(((nh * 8 + in) << 3) + ki) * 32 + lane]);

        uint4 aq0 = *(const uint4*)((const char*)XsF +
                     (size_t)((mq * 2 + 0) * 8 + ki) * 528 + lane * 16);
        uint4 aq1 = *(const uint4*)((const char*)XsF +
                     (size_t)((mq * 2 + 1) * 8 + ki) * 528 + lane * 16);

        #pragma unroll
        for (int in = 0; in < 8; in++) {
            mma_f16(acc[0][in][0], acc[0][in][1], acc[0][in][2], acc[0][in][3],
                    aq0.x, aq0.y, aq0.z, aq0.w, bf[in].x, bf[in].y);
            mma_f16(acc[1][in][0], acc[1][in][1], acc[1][in][2], acc[1][in][3],
                    aq1.x, aq1.y, aq1.z, aq1.w, bf[in].x, bf[in].y);
        }
    }

    // epilogue: relu(D+b2)*W3, reduce per edge
    #pragma unroll
    for (int im = 0; im < 2; im++) {
        float p0 = 0.0f, p1 = 0.0f;
        #pragma unroll
        for (int in = 0; in < 8; in++) {
            const int col0 = nh * 64 + in * 8 + 2 * t;
            const float bb0 = b2s[col0], bb1 = b2s[col0 + 1];
            const float w0  = w3s[col0], w1  = w3s[col0 + 1];
            p0 = fmaf(fmaxf(acc[im][in][0] + bb0, 0.f), w0, p0);
            p0 = fmaf(fmaxf(acc[im][in][1] + bb1, 0.f), w1, p0);
            p1 = fmaf(fmaxf(acc[im][in][2] + bb0, 0.f), w0, p1);
            p1 = fmaf(fmaxf(acc[im][in][3] + bb1, 0.f), w1, p1);
        }
        p0 += __shfl_xor_sync(0xFFFFFFFFu, p0, 1);
        p0 += __shfl_xor_sync(0xFFFFFFFFu, p0, 2);
        p1 += __shfl_xor_sync(0xFFFFFFFFu, p1, 1);
        p1 += __shfl_xor_sync(0xFFFFFFFFu, p1, 2);
        if (t == 0) {
            atomicAdd(&esum[mq * 32 + im * 16 + g],     p0);
            atomicAdd(&esum[mq * 32 + im * 16 + g + 8], p1);
        }
    }
    __syncthreads();

    if (tid < 128) {
        const int e = base + tid;
        if (e < n_edges) out[e] = esum[tid];
    }
}

// ===========================================================================
// launch: inputs: h, src, dst, W1, b1, W2, b2, W3, b3 ; out: [n_edges] f32
// ===========================================================================
extern "C" void kernel_launch(void* const* d_in, const int* in_sizes, int n_in,
                              void* d_out, int out_size)
{
    const float* h   = (const float*)d_in[0];
    const int*   src = (const int*)  d_in[1];
    const int*   dst = (const int*)  d_in[2];
    const float* W1  = (const float*)d_in[3];
    const float* b1  = (const float*)d_in[4];
    const float* W2  = (const float*)d_in[5];
    const float* b2  = (const float*)d_in[6];
    const float* W3  = (const float*)d_in[7];
    const float* b3  = (const float*)d_in[8];
    float*       out = (float*)d_out;

    const int n_nodes = in_sizes[0] / F;
    const int n_edges = in_sizes[1];

    cudaFuncSetAttribute(node_mma_kernel,
                         cudaFuncAttributeMaxDynamicSharedMemorySize, NODE_SMEM_B);
    cudaFuncSetAttribute(edge_mma_kernel,
                         cudaFuncAttributeMaxDynamicSharedMemorySize, EDGE_SMEM_B);

    pack_w2_kernel<<<16, 256>>>(W2);
    pack_w1_kernel<<<32, 256>>>(W1);

    const int gridA = (n_nodes + 127) / 128;
    node_mma_kernel<<<gridA, 256, NODE_SMEM_B>>>(h, b1, n_nodes);

    const int gridB = (n_edges + 127) / 128;
    edge_mma_kernel<<<gridB, 256, EDGE_SMEM_B>>>(src, dst, b2, W3, b3, out, n_edges);
}

// round 8
// speedup vs baseline: 7.6921x; 1.3956x over previous
#include <cuda_runtime.h>
#include <cuda_fp16.h>
#include <cstdint>

#define NN_MAX   100000
#define F        128

// Scratch (fp16): A[n][j] = W1[:,:128]@h[n] + b1 ; B[n][j] = W1[:,128:]@h[n]
__device__ __half g_Ah[NN_MAX * F];
__device__ __half g_Bh[NN_MAX * F];

// fp16 b-fragments for m16n8k16 (row.col):
//   b0 = {W[n][kc+2t], W[n][kc+2t+1]}, b1 = {W[n][kc+2t+8], W[n][kc+2t+9]},
//   n = ni*8 + (lane>>2), kc = ki16*16
__device__ uint2 g_W2f[16 * 8 * 32];
__device__ uint2 g_W1f[32 * 8 * 32];

// ---------------------------------------------------------------------------
__device__ __forceinline__ uint32_t h2pack(float lo, float hi) {
    __half2 h = __floats2half2_rn(lo, hi);
    return *reinterpret_cast<uint32_t*>(&h);
}
__device__ __forceinline__ uint32_t h2u(__half2 h) {
    return *reinterpret_cast<uint32_t*>(&h);
}
// relu(a+b)*mask on packed half2 (inputs as raw u32)
__device__ __forceinline__ __half2 combh2(uint32_t a, uint32_t b, __half2 m) {
    __half2 ha = *reinterpret_cast<__half2*>(&a);
    __half2 hb = *reinterpret_cast<__half2*>(&b);
    const __half2 z = __float2half2_rn(0.0f);
    return __hmul2(__hmax2(__hadd2(ha, hb), z), m);
}

__device__ __forceinline__ void mma_f16(float& c0, float& c1, float& c2, float& c3,
                                        uint32_t a0, uint32_t a1, uint32_t a2, uint32_t a3,
                                        uint32_t b0, uint32_t b1)
{
    asm volatile(
        "mma.sync.aligned.m16n8k16.row.col.f32.f16.f16.f32 "
        "{%0,%1,%2,%3}, {%4,%5,%6,%7}, {%8,%9}, {%0,%1,%2,%3};\n"
        : "+f"(c0), "+f"(c1), "+f"(c2), "+f"(c3)
        : "r"(a0), "r"(a1), "r"(a2), "r"(a3), "r"(b0), "r"(b1));
}

// ===========================================================================
// Prep kernels
// ===========================================================================
__global__ void pack_w2_kernel(const float* __restrict__ W2)
{
    const int idx  = blockIdx.x * blockDim.x + threadIdx.x;
    if (idx >= 16 * 8 * 32) return;
    const int lane = idx & 31;
    const int ki   = (idx >> 5) & 7;
    const int ni   = idx >> 8;
    const int g    = lane >> 2;
    const int t    = lane & 3;
    const float* w = W2 + (size_t)(ni * 8 + g) * F + ki * 16;
    uint2 v;
    v.x = h2pack(__ldg(&w[2 * t]),     __ldg(&w[2 * t + 1]));
    v.y = h2pack(__ldg(&w[2 * t + 8]), __ldg(&w[2 * t + 9]));
    g_W2f[idx] = v;
}

__global__ void pack_w1_kernel(const float* __restrict__ W1)
{
    const int idx  = blockIdx.x * blockDim.x + threadIdx.x;
    if (idx >= 32 * 8 * 32) return;
    const int lane = idx & 31;
    const int ki   = (idx >> 5) & 7;
    const int ni   = idx >> 8;
    const int g    = lane >> 2;
    const int t    = lane & 3;
    const int j2   = ni * 8 + g;
    const float* w = W1 + (size_t)(j2 & 127) * 256 + ((j2 >> 7) << 7) + ki * 16;
    uint2 v;
    v.x = h2pack(__ldg(&w[2 * t]),     __ldg(&w[2 * t + 1]));
    v.y = h2pack(__ldg(&w[2 * t + 8]), __ldg(&w[2 * t + 9]));
    g_W1f[idx] = v;
}

// ===========================================================================
// fp16 fragment tile layout: tile = mi*8 + ki16 (mi 0..7, ki16 0..7),
// stride 528 B; lane (g,t) uint4 = {h2 row(g) k(2t), h2 row(g+8) k(2t),
//                                   h2 row(g) k(2t+8), h2 row(g+8) k(2t+8)}
// ===========================================================================
#define XSF_WORDS   (64 * 132)

// ===========================================================================
// Node kernel: [A|B] = h @ W1^T -> fp16 g_Ah/g_Bh
// ===========================================================================
#define NODE_SMEM_B ((XSF_WORDS + 128) * 4 + 16)

__global__ void __launch_bounds__(256, 2)
node_mma_kernel(const float* __restrict__ h,
                const float* __restrict__ b1,
                int n_nodes)
{
    extern __shared__ uint32_t sm[];
    uint32_t* HsF = sm;
    float*    b1s = (float*)(sm + XSF_WORDS);

    const int tid  = threadIdx.x;
    const int lane = tid & 31;
    const int warp = tid >> 5;
    const int g    = lane >> 2;
    const int t    = lane & 3;
    const int base = blockIdx.x * 128;

    if (tid < 128) b1s[tid] = __ldg(&b1[tid]);

    #pragma unroll
    for (int p = 0; p < 2; p++) {
        const int tile = p * 32 + warp * 4 + (lane & 3);
        const int gg   = lane >> 2;
        const int mi   = tile >> 3;
        const int kc   = (tile & 7) * 16;
        const int rA   = mi * 16 + gg;
        const int rB   = rA + 8;
        const float mA = ((base + rA) < n_nodes) ? 1.0f : 0.0f;
        const float mB = ((base + rB) < n_nodes) ? 1.0f : 0.0f;
        const int  nA  = ((base + rA) < n_nodes) ? (base + rA) : 0;
        const int  nB  = ((base + rB) < n_nodes) ? (base + rB) : 0;

        float xA[16], xB[16];
        {
            const float4* pa = (const float4*)(h + (size_t)nA * F + kc);
            const float4* pb = (const float4*)(h + (size_t)nB * F + kc);
            #pragma unroll
            for (int q = 0; q < 4; q++) {
                float4 a = __ldg(pa + q);
                float4 b = __ldg(pb + q);
                xA[q*4+0] = a.x * mA; xA[q*4+1] = a.y * mA;
                xA[q*4+2] = a.z * mA; xA[q*4+3] = a.w * mA;
                xB[q*4+0] = b.x * mB; xB[q*4+1] = b.y * mB;
                xB[q*4+2] = b.z * mB; xB[q*4+3] = b.w * mB;
            }
        }

        char* tb = (char*)HsF + (size_t)tile * 528 + gg * 64;
        #pragma unroll
        for (int j = 0; j < 4; j++) {
            uint4 q;
            q.x = h2pack(xA[2*j],     xA[2*j + 1]);
            q.y = h2pack(xB[2*j],     xB[2*j + 1]);
            q.z = h2pack(xA[2*j + 8], xA[2*j + 9]);
            q.w = h2pack(xB[2*j + 8], xB[2*j + 9]);
            *(uint4*)(tb + j * 16) = q;
        }
    }
    __syncthreads();

    const int mq = warp & 3;

    for (int np = (warp >> 2); np < 4; np += 2) {
        float acc[2][8][4];
        #pragma unroll
        for (int im = 0; im < 2; im++)
            #pragma unroll
            for (int in = 0; in < 8; in++)
                #pragma unroll
                for (int c = 0; c < 4; c++) acc[im][in][c] = 0.0f;

        #pragma unroll
        for (int ki = 0; ki < 8; ki++) {
            uint2 bf[8];
            #pragma unroll
            for (int in = 0; in < 8; in++)
                bf[in] = __ldg(&g_W1f[(((np * 8 + in) << 3) + ki) * 32 + lane]);

            uint4 aq0 = *(const uint4*)((const char*)HsF +
                         (size_t)((mq * 2 + 0) * 8 + ki) * 528 + lane * 16);
            uint4 aq1 = *(const uint4*)((const char*)HsF +
                         (size_t)((mq * 2 + 1) * 8 + ki) * 528 + lane * 16);

            #pragma unroll
            for (int in = 0; in < 8; in++) {
                mma_f16(acc[0][in][0], acc[0][in][1], acc[0][in][2], acc[0][in][3],
                        aq0.x, aq0.y, aq0.z, aq0.w, bf[in].x, bf[in].y);
                mma_f16(acc[1][in][0], acc[1][in][1], acc[1][in][2], acc[1][in][3],
                        aq1.x, aq1.y, aq1.z, aq1.w, bf[in].x, bf[in].y);
            }
        }

        const int nb = np * 64;
        #pragma unroll
        for (int im = 0; im < 2; im++) {
            const int r0 = mq * 32 + im * 16 + g;
            const int n0 = base + r0;
            const int n1 = n0 + 8;
            #pragma unroll
            for (int in = 0; in < 8; in++) {
                const int col0 = nb + in * 8 + 2 * t;
                const bool isA = (col0 < 128);
                const float bb0 = isA ? b1s[col0]     : 0.0f;
                const float bb1 = isA ? b1s[col0 + 1] : 0.0f;
                __half* dst = isA ? g_Ah : g_Bh;
                const int  cc  = isA ? col0 : (col0 - 128);
                if (n0 < n_nodes) {
                    __half2 v = __floats2half2_rn(acc[im][in][0] + bb0,
                                                  acc[im][in][1] + bb1);
                    *(__half2*)(dst + (size_t)n0 * F + cc) = v;
                }
                if (n1 < n_nodes) {
                    __half2 v = __floats2half2_rn(acc[im][in][2] + bb0,
                                                  acc[im][in][3] + bb1);
                    *(__half2*)(dst + (size_t)n1 * F + cc) = v;
                }
            }
        }
    }
}

// ===========================================================================
// Edge kernel: x = relu(Ah[src]+Bh[dst]) (half2); D = x @ W2^T (fp16 mma);
// out = relu(D+b2)@W3 + b3.
// ===========================================================================
#define EDGE_SMEM_B ((XSF_WORDS + 128 * 5) * 4 + 16)

__global__ void __launch_bounds__(256, 2)
edge_mma_kernel(const int*   __restrict__ src,
                const int*   __restrict__ dst,
                const float* __restrict__ b2,
                const float* __restrict__ W3,
                const float* __restrict__ b3,
                float*       __restrict__ out,
                int n_edges)
{
    extern __shared__ uint32_t sm[];
    uint32_t* XsF  = sm;
    int*      ss   = (int*)(sm + XSF_WORDS);
    int*      ds   = ss + 128;
    float*    b2s  = (float*)(ds + 128);
    float*    w3s  = b2s + 128;
    float*    esum = w3s + 128;

    const int tid  = threadIdx.x;
    const int lane = tid & 31;
    const int warp = tid >> 5;
    const int g    = lane >> 2;
    const int t    = lane & 3;
    const int base = blockIdx.x * 128;

    if (tid < 128) {
        const int e = base + tid;
        const bool ok = (e < n_edges);
        ss[tid]   = ok ? __ldg(&src[e]) : 0;
        ds[tid]   = ok ? __ldg(&dst[e]) : 0;
        b2s[tid]  = __ldg(&b2[tid]);
        w3s[tid]  = __ldg(&W3[tid]);
        esum[tid] = __ldg(&b3[0]);
    }
    __syncthreads();

    // producer: half2 gather + relu -> fragment layout
    #pragma unroll
    for (int p = 0; p < 2; p++) {
        const int tile = p * 32 + warp * 4 + (lane & 3);
        const int gg   = lane >> 2;
        const int mi   = tile >> 3;
        const int kc   = (tile & 7) * 16;
        const int rA   = mi * 16 + gg;
        const int rB   = rA + 8;
        const __half2 mA = __float2half2_rn(((base + rA) < n_edges) ? 1.0f : 0.0f);
        const __half2 mB = __float2half2_rn(((base + rB) < n_edges) ? 1.0f : 0.0f);

        __half2 pA[8], pB[8];
        {
            const uint4* pa = (const uint4*)(g_Ah + (size_t)ss[rA] * F + kc);
            const uint4* pb = (const uint4*)(g_Bh + (size_t)ds[rA] * F + kc);
            uint4 a0 = __ldg(pa), a1 = __ldg(pa + 1);
            uint4 b0 = __ldg(pb), b1 = __ldg(pb + 1);
            pA[0] = combh2(a0.x, b0.x, mA); pA[1] = combh2(a0.y, b0.y, mA);
            pA[2] = combh2(a0.z, b0.z, mA); pA[3] = combh2(a0.w, b0.w, mA);
            pA[4] = combh2(a1.x, b1.x, mA); pA[5] = combh2(a1.y, b1.y, mA);
            pA[6] = combh2(a1.z, b1.z, mA); pA[7] = combh2(a1.w, b1.w, mA);
        }
        {
            const uint4* pa = (const uint4*)(g_Ah + (size_t)ss[rB] * F + kc);
            const uint4* pb = (const uint4*)(g_Bh + (size_t)ds[rB] * F + kc);
            uint4 a0 = __ldg(pa), a1 = __ldg(pa + 1);
            uint4 b0 = __ldg(pb), b1 = __ldg(pb + 1);
            pB[0] = combh2(a0.x, b0.x, mB); pB[1] = combh2(a0.y, b0.y, mB);
            pB[2] = combh2(a0.z, b0.z, mB); pB[3] = combh2(a0.w, b0.w, mB);
            pB[4] = combh2(a1.x, b1.x, mB); pB[5] = combh2(a1.y, b1.y, mB);
            pB[6] = combh2(a1.z, b1.z, mB); pB[7] = combh2(a1.w, b1.w, mB);
        }

        char* tb = (char*)XsF + (size_t)tile * 528 + gg * 64;
        #pragma unroll
        for (int j = 0; j < 4; j++) {
            uint4 q;
            q.x = h2u(pA[j]);     q.y = h2u(pB[j]);
            q.z = h2u(pA[j + 4]); q.w = h2u(pB[j + 4]);
            *(uint4*)(tb + j * 16) = q;
        }
    }
    __syncthreads();

    const int mq = warp & 3;
    const int nh = warp >> 2;

    float acc[2][8][4];
    #pragma unroll
    for (int im = 0; im < 2; im++)
        #pragma unroll
        for (int in = 0; in < 8; in++)
            #pragma unroll
            for (int c = 0; c < 4; c++) acc[im][in][c] = 0.0f;

    #pragma unroll
    for (int ki = 0; ki < 8; ki++) {
        uint2 bf[8];
        #pragma unroll
        for (int in = 0; in < 8; in++)
            bf[in] = __ldg(&g_W2f[(((nh * 8 + in) << 3) + ki) * 32 + lane]);

        uint4 aq0 = *(const uint4*)((const char*)XsF +
                     (size_t)((mq * 2 + 0) * 8 + ki) * 528 + lane * 16);
        uint4 aq1 = *(const uint4*)((const char*)XsF +
                     (size_t)((mq * 2 + 1) * 8 + ki) * 528 + lane * 16);

        #pragma unroll
        for (int in = 0; in < 8; in++) {
            mma_f16(acc[0][in][0], acc[0][in][1], acc[0][in][2], acc[0][in][3],
                    aq0.x, aq0.y, aq0.z, aq0.w, bf[in].x, bf[in].y);
            mma_f16(acc[1][in][0], acc[1][in][1], acc[1][in][2], acc[1][in][3],
                    aq1.x, aq1.y, aq1.z, aq1.w, bf[in].x, bf[in].y);
        }
    }

    #pragma unroll
    for (int im = 0; im < 2; im++) {
        float p0 = 0.0f, p1 = 0.0f;
        #pragma unroll
        for (int in = 0; in < 8; in++) {
            const int col0 = nh * 64 + in * 8 + 2 * t;
            const float bb0 = b2s[col0], bb1 = b2s[col0 + 1];
            const float w0  = w3s[col0], w1  = w3s[col0 + 1];
            p0 = fmaf(fmaxf(acc[im][in][0] + bb0, 0.f), w0, p0);
            p0 = fmaf(fmaxf(acc[im][in][1] + bb1, 0.f), w1, p0);
            p1 = fmaf(fmaxf(acc[im][in][2] + bb0, 0.f), w0, p1);
            p1 = fmaf(fmaxf(acc[im][in][3] + bb1, 0.f), w1, p1);
        }
        p0 += __shfl_xor_sync(0xFFFFFFFFu, p0, 1);
        p0 += __shfl_xor_sync(0xFFFFFFFFu, p0, 2);
        p1 += __shfl_xor_sync(0xFFFFFFFFu, p1, 1);
        p1 += __shfl_xor_sync(0xFFFFFFFFu, p1, 2);
        if (t == 0) {
            atomicAdd(&esum[mq * 32 + im * 16 + g],     p0);
            atomicAdd(&esum[mq * 32 + im * 16 + g + 8], p1);
        }
    }
    __syncthreads();

    if (tid < 128) {
        const int e = base + tid;
        if (e < n_edges) out[e] = esum[tid];
    }
}

// ===========================================================================
// launch: inputs: h, src, dst, W1, b1, W2, b2, W3, b3 ; out: [n_edges] f32
// ===========================================================================
extern "C" void kernel_launch(void* const* d_in, const int* in_sizes, int n_in,
                              void* d_out, int out_size)
{
    const float* h   = (const float*)d_in[0];
    const int*   src = (const int*)  d_in[1];
    const int*   dst = (const int*)  d_in[2];
    const float* W1  = (const float*)d_in[3];
    const float* b1  = (const float*)d_in[4];
    const float* W2  = (const float*)d_in[5];
    const float* b2  = (const float*)d_in[6];
    const float* W3  = (const float*)d_in[7];
    const float* b3  = (const float*)d_in[8];
    float*       out = (float*)d_out;

    const int n_nodes = in_sizes[0] / F;
    const int n_edges = in_sizes[1];

    cudaFuncSetAttribute(node_mma_kernel,
                         cudaFuncAttributeMaxDynamicSharedMemorySize, NODE_SMEM_B);
    cudaFuncSetAttribute(edge_mma_kernel,
                         cudaFuncAttributeMaxDynamicSharedMemorySize, EDGE_SMEM_B);

    pack_w2_kernel<<<16, 256>>>(W2);
    pack_w1_kernel<<<32, 256>>>(W1);

    const int gridA = (n_nodes + 127) / 128;
    node_mma_kernel<<<gridA, 256, NODE_SMEM_B>>>(h, b1, n_nodes);

    const int gridB = (n_edges + 127) / 128;
    edge_mma_kernel<<<gridB, 256, EDGE_SMEM_B>>>(src, dst, b2, W3, b3, out, n_edges);
}